// round 4
// baseline (speedup 1.0000x reference)
#include <cuda_runtime.h>

#define LN_EPS 1e-5f
#define D_EPS  1e-6f
#define BATCH  16
#define SEQL   2048

// Padded/reversed step stream: 8 warmup dummies + 2047 real + 1 tail dummy
#define NSTEP  2056
#define NREC   2064

// Scratch
__device__ float g_tab[64 * 64];   // per-token post-LN hidden vector
__device__ float g_G[64 * 64];     // Gram: G[a][c] = tab_a . tab_c
__device__ float g_TW[64 * 64];    // Tab @ Wr
__device__ float g_rneg[64];       // -1/(||tab_a||^2 + D_EPS)
__device__ float g_dneg[64];       // -(||tab_a||^2 + D_EPS)

// ---------------------------------------------------------------------------
// K1: per-token table: tab[a] = LN(e_a + MLP(e_a)); also dneg/rneg.
// ---------------------------------------------------------------------------
__global__ __launch_bounds__(128) void table_kernel(
    const float* __restrict__ embed, const float* __restrict__ W1,
    const float* __restrict__ b1, const float* __restrict__ W2,
    const float* __restrict__ b2, const float* __restrict__ gamma,
    const float* __restrict__ beta)
{
    __shared__ float hs[64];
    __shared__ float t1s[128];
    __shared__ float xh[2][64];
    __shared__ float red[2][2];

    const int a = blockIdx.x, tid = threadIdx.x;
    if (tid < 64) hs[tid] = embed[a * 64 + tid];
    __syncthreads();

    float acc = b1[tid];
    #pragma unroll
    for (int i = 0; i < 64; i++) acc = fmaf(hs[i], W1[i * 128 + tid], acc);
    t1s[tid] = fmaxf(acc, 0.f);
    __syncthreads();

    {
        int j = tid & 63, half = tid >> 6;
        float a2 = 0.f;
        #pragma unroll
        for (int ii = 0; ii < 64; ii++) {
            int i = half * 64 + ii;
            a2 = fmaf(t1s[i], W2[i * 64 + j], a2);
        }
        xh[half][j] = a2;
    }
    __syncthreads();

    float x = 0.f, y = 0.f;
    if (tid < 64) {
        x = hs[tid] + xh[0][tid] + xh[1][tid] + b2[tid];
        float s = x, q = x * x;
        #pragma unroll
        for (int o = 16; o > 0; o >>= 1) {
            s += __shfl_xor_sync(0xffffffffu, s, o);
            q += __shfl_xor_sync(0xffffffffu, q, o);
        }
        if ((tid & 31) == 0) { red[tid >> 5][0] = s; red[tid >> 5][1] = q; }
    }
    __syncthreads();
    if (tid < 64) {
        float S = red[0][0] + red[1][0];
        float Q = red[0][1] + red[1][1];
        float mu = S * (1.0f / 64.0f);
        float var = Q * (1.0f / 64.0f) - mu * mu;
        y = (x - mu) * rsqrtf(var + LN_EPS) * gamma[tid] + beta[tid];
        g_tab[a * 64 + tid] = y;
        float z = y * y;
        #pragma unroll
        for (int o = 16; o > 0; o >>= 1) z += __shfl_xor_sync(0xffffffffu, z, o);
        if ((tid & 31) == 0) red[tid >> 5][0] = z;
    }
    __syncthreads();
    if (tid == 0) {
        float ss = red[0][0] + red[1][0];
        float d = ss + D_EPS;
        g_dneg[a] = -d;
        g_rneg[a] = -1.0f / d;
    }
}

// ---------------------------------------------------------------------------
// K2: G = Tab Tab^T and TW = Tab @ Wr. 64 blocks x 64 threads.
// ---------------------------------------------------------------------------
__global__ __launch_bounds__(64) void gram_kernel(const float* __restrict__ Wr)
{
    __shared__ float T[64][65];
    const int a = blockIdx.x, t = threadIdx.x;
    for (int r = 0; r < 64; r++) T[r][t] = g_tab[r * 64 + t];
    __syncthreads();
    float g = 0.f, tw = 0.f;
    #pragma unroll
    for (int h = 0; h < 64; h++) {
        float av = T[a][h];
        g  = fmaf(av, T[t][h], g);
        tw = fmaf(av, Wr[h * 64 + t], tw);
    }
    g_G[a * 64 + t]  = g;
    g_TW[a * 64 + t] = tw;
}

// ---------------------------------------------------------------------------
// K3: scan + head, 1 block per batch, 256 threads.
// Phase A (all): stage G, reversed token stream v, rn table.
// Phase B (all): per-step records: {C1,C2,C3,RN} with Ck = rn_i*G[v_i][v_{i-k}],
//                {idx, odd} for the shfl, v for the post-pass.
// Phase C (warp 0): depth-4 pipelined scalar scan, cm_i streamed to smem.
// Phase D (all): beta[a] = dn_a * sum_{v_i=a} cm_i; head GEMV -> out.
// ---------------------------------------------------------------------------
// smem float offsets
#define OFF_G   0                 // 4096
#define OFF_RA  4096              // 2064*4 float4 records
#define OFF_IO  12352             // 2064*2 int2 {idx, odd}
#define OFF_VS  16480             // 2064 int v
#define OFF_CM  18544             // 2064 float cm
#define OFF_RN  20608             // 64
#define OFF_PT  20672             // 4*64 partials
#define OFF_BT  20928             // 64 beta
#define SMEM_FLOATS 20992
#define SMEM_BYTES  (SMEM_FLOATS * 4)

__global__ __launch_bounds__(256) void scan_kernel(
    const int* __restrict__ seq,
    const float* __restrict__ br, const float* __restrict__ Wo,
    const float* __restrict__ bo, float* __restrict__ out)
{
    extern __shared__ float sm[];
    float* Gsh  = sm + OFF_G;
    float4* RAp = (float4*)(sm + OFF_RA);
    int2*   IOp = (int2*)(sm + OFF_IO);
    int*    VSp = (int*)(sm + OFF_VS);
    float*  CMp = sm + OFF_CM;
    float*  rnsh = sm + OFF_RN;
    float*  part = sm + OFF_PT;
    float*  betash = sm + OFF_BT;

    const int b = blockIdx.x;
    const int tid = threadIdx.x;
    const int* sq = seq + b * SEQL;

    // ---- Phase A: stage ----
    for (int e = tid; e < 4096; e += 256) Gsh[e] = g_G[e];
    if (tid < 64) rnsh[tid] = g_rneg[tid];
    for (int i = tid; i < NREC; i += 256) {
        int v = 0;
        if (i >= 8 && i < 8 + 2047) v = sq[2046 - (i - 8)];
        VSp[i] = v;
    }
    __syncthreads();

    // ---- Phase B: records ----
    for (int i = tid; i < NREC; i += 256) {
        int v = VSp[i];
        bool real = (i >= 8 && i < 8 + 2047);
        float rn = real ? rnsh[v] : 0.f;
        const float* grow = &Gsh[v * 64];
        float c1 = (real && i >= 9)  ? rn * grow[VSp[i - 1]] : 0.f;
        float c2 = (real && i >= 10) ? rn * grow[VSp[i - 2]] : 0.f;
        float c3 = (real && i >= 11) ? rn * grow[VSp[i - 3]] : 0.f;
        RAp[i] = make_float4(c1, c2, c3, rn);
        IOp[i] = make_int2(v >> 1, v & 1);
    }
    __syncthreads();

    // ---- Phase C: warp 0 scan ----
    if (tid < 32) {
        const int l = tid;
        const int vq = sq[SEQL - 1];
        float w0 = Gsh[(2 * l) * 64 + vq];
        float w1 = Gsh[(2 * l + 1) * 64 + vq];
        const float2* Gl = (const float2*)&Gsh[2 * l];   // [row v] -> Gl[v*32]

        float4 rotA[8]; int2 rotIO[8]; int rotV[8]; float2 rotGP[8];
        float Abuf[8], T2b[8], T1b[8];
        #pragma unroll
        for (int j = 0; j < 8; j++) {
            rotA[j] = make_float4(0.f, 0.f, 0.f, 0.f);
            rotIO[j] = make_int2(0, 0);
            rotV[j] = 0;
            rotGP[j] = make_float2(0.f, 0.f);
            Abuf[j] = 0.f; T2b[j] = 0.f; T1b[j] = 0.f;
        }
        #pragma unroll
        for (int j = 0; j < 6; j++) {
            rotA[j] = RAp[j];
            rotIO[j] = IOp[j];
            rotV[j] = VSp[j];
        }
        #pragma unroll
        for (int j = 0; j < 3; j++) rotGP[j] = Gl[rotV[j] * 32];

        float cm = 0.f;
        const bool lead = (l == 0);

        #pragma unroll 8
        for (int i = 0; i < NSTEP; i++) {
            const int s0 = i & 7, s2 = (i + 2) & 7, s3 = (i + 3) & 7;
            const int s4 = (i + 4) & 7, s6 = (i + 6) & 7;
            cm = fmaf(cm, rotA[s0].x, T1b[s0]);
            if (lead) CMp[i] = cm;
            w0 = fmaf(cm, rotGP[s0].x, w0);
            w1 = fmaf(cm, rotGP[s0].y, w1);
            float ws = rotIO[s4].y ? w1 : w0;
            Abuf[s4] = __shfl_sync(0xffffffffu, ws, rotIO[s4].x);
            float P = rotA[s3].w * Abuf[s3];
            T2b[s3] = fmaf(cm, rotA[s3].z, P);
            T1b[s2] = fmaf(cm, rotA[s2].y, T2b[s2]);
            rotGP[s3] = Gl[rotV[s3] * 32];
            rotA[s6] = RAp[i + 6];
            rotIO[s6] = IOp[i + 6];
            rotV[s6] = VSp[i + 6];
        }
    }
    __syncthreads();

    // ---- Phase D: beta gather + head ----
    {
        const int a = tid & 63, qd = tid >> 6;
        float p = 0.f;
        for (int i = qd * 4; i < NSTEP; i += 16) {
            float4 c = *(const float4*)&CMp[i];
            int4 vv = *(const int4*)&VSp[i];
            if (vv.x == a) p += c.x;
            if (vv.y == a) p += c.y;
            if (vv.z == a) p += c.z;
            if (vv.w == a) p += c.w;
        }
        part[qd * 64 + a] = p;
    }
    __syncthreads();
    if (tid < 64) {
        float s = part[tid] + part[64 + tid] + part[128 + tid] + part[192 + tid];
        betash[tid] = s * g_dneg[tid];
    }
    __syncthreads();
    if (tid < 64) {
        const int j = tid;
        float acc = br[j];
        #pragma unroll
        for (int a = 0; a < 64; a++) acc = fmaf(betash[a], g_TW[a * 64 + j], acc);
        part[j] = acc;          // reuse as rsh
    }
    __syncthreads();
    if (tid < 64) {
        const int j = tid;
        float o = bo[j];
        #pragma unroll
        for (int k = 0; k < 64; k++) o = fmaf(part[k], Wo[k * 64 + j], o);
        out[b * 64 + j] = o;
    }
}

// ---------------------------------------------------------------------------
extern "C" void kernel_launch(void* const* d_in, const int* in_sizes, int n_in,
                              void* d_out, int out_size)
{
    const int*   seq   = (const int*)d_in[0];
    const float* embed = (const float*)d_in[1];
    const float* W1    = (const float*)d_in[2];
    const float* b1    = (const float*)d_in[3];
    const float* W2    = (const float*)d_in[4];
    const float* b2    = (const float*)d_in[5];
    const float* gamma = (const float*)d_in[6];
    const float* beta  = (const float*)d_in[7];
    const float* Wr    = (const float*)d_in[8];
    const float* br    = (const float*)d_in[9];
    const float* Wo    = (const float*)d_in[10];
    const float* bo    = (const float*)d_in[11];
    float* out = (float*)d_out;

    static bool attr_done = false;
    if (!attr_done) {
        cudaFuncSetAttribute(scan_kernel,
                             cudaFuncAttributeMaxDynamicSharedMemorySize,
                             SMEM_BYTES);
        attr_done = true;
    }

    table_kernel<<<64, 128>>>(embed, W1, b1, W2, b2, gamma, beta);
    gram_kernel<<<64, 64>>>(Wr);
    scan_kernel<<<BATCH, 256, SMEM_BYTES>>>(seq, br, Wo, bo, out);
}